// round 14
// baseline (speedup 1.0000x reference)
#include <cuda_runtime.h>
#include <cuda_fp16.h>
#include <cstdint>

#define B_   16
#define T_   1024
#define E_   256
#define NB_  1025
#define BT_  16384
#define NE_  1024

#define ZQ_SIZE  (BT_ * E_)
#define LOSS_OFF ZQ_SIZE
#define IND_OFF  (ZQ_SIZE + 1)
#define V_OFF    (IND_OFF + BT_)

#define DSTRIDE  1024
#define NTILES_N 8               // 8 * 128 = 1024 cols (col 1024 handled in k_post)
#define NTILES_R 128             // 128-row chunks, t-chunk-major: rb = tc*16 + b
#define NGEMM    (NTILES_N * NTILES_R)
#define NPOST    2048

#define K_EXT    256             // plain fp16 GEMM + hybrid-precision scan
#define KCH      32
#define NCH      (K_EXT / KCH)   // 8
#define ASTRIDE  40              // half elements per smem row (80 B)

#define THETA    2e-4f           // scan recompute trigger (~12 sigma of fp16-d err)

typedef unsigned long long ull;

__device__ int    g_ind[BT_];
__device__ int    g_sink[B_];
__device__ float  g_zsq[BT_];
__device__ float  g_bsq[1152];
__device__ float  g_d[(size_t)(BT_ + 16) * DSTRIDE];   // padded rows for scan tail
__device__ double g_part[NPOST];
__device__ int    g_rowflag[NTILES_R];
__device__ __half a_ext[(size_t)BT_ * K_EXT];   // 8 MB
__device__ __half b_ext[(size_t)NB_ * K_EXT];   // 0.5 MB

static __device__ __forceinline__ float warp_sum(float v) {
#pragma unroll
    for (int o = 16; o > 0; o >>= 1) v += __shfl_xor_sync(0xffffffffu, v, o);
    return v;
}

static __device__ __forceinline__ uint32_t smem_u32(const void* p) {
    uint32_t a;
    asm("{ .reg .u64 t; cvta.to.shared.u64 t, %1; cvt.u32.u64 %0, t; }"
        : "=r"(a) : "l"(p));
    return a;
}

static __device__ __forceinline__ int ld_acq(const int* p) {
    int v;
    asm volatile("ld.acquire.gpu.global.s32 %0, [%1];" : "=r"(v) : "l"(p) : "memory");
    return v;
}

#define CP16(dst, src) \
    asm volatile("cp.async.cg.shared.global [%0], [%1], 16;" :: "r"(dst), "l"(src))
#define CPCOMMIT() asm volatile("cp.async.commit_group;" ::: "memory")
#define CPWAIT(N)  asm volatile("cp.async.wait_group %0;" :: "n"(N) : "memory")

#define LDSM4(r0, r1, r2, r3, addr) \
    asm volatile("ldmatrix.sync.aligned.m8n8.x4.shared.b16 {%0,%1,%2,%3}, [%4];" \
                 : "=r"(r0), "=r"(r1), "=r"(r2), "=r"(r3) : "r"(addr))

static __device__ __forceinline__ void mma16816(float* c, const unsigned* a,
                                                unsigned b0, unsigned b1) {
    asm volatile(
        "mma.sync.aligned.m16n8k16.row.col.f32.f16.f16.f32 "
        "{%0,%1,%2,%3}, {%4,%5,%6,%7}, {%8,%9}, {%0,%1,%2,%3};"
        : "+f"(c[0]), "+f"(c[1]), "+f"(c[2]), "+f"(c[3])
        : "r"(a[0]), "r"(a[1]), "r"(a[2]), "r"(a[3]), "r"(b0), "r"(b1));
}

// ---------------------------------------------------------------------------
// k_prep: fused row norms + fp16 convert + flag reset.
// ---------------------------------------------------------------------------
__global__ void k_prep(const float* __restrict__ z, const float* __restrict__ w) {
    if (blockIdx.x == 0 && threadIdx.x < NTILES_R) g_rowflag[threadIdx.x] = 0;
    int gw = (blockIdx.x * blockDim.x + threadIdx.x) >> 5;
    int lane = threadIdx.x & 31;
    if (gw >= BT_ + NB_) return;

    const float* src = (gw < BT_) ? (z + (size_t)gw * E_ + lane * 8)
                                  : (w + (size_t)(gw - BT_) * E_ + lane * 8);
    float4 a = *(const float4*)src;
    float4 b = *(const float4*)(src + 4);
    float f[8] = {a.x, a.y, a.z, a.w, b.x, b.y, b.z, b.w};

    float s = 0.0f;
    union { __half h[8]; uint4 v; } hi;
#pragma unroll
    for (int j = 0; j < 8; j++) {
        s += f[j] * f[j];
        hi.h[j] = __float2half_rn(f[j]);
    }
    s = warp_sum(s);

    if (gw < BT_) {
        *(uint4*)(a_ext + (size_t)gw * K_EXT + lane * 8) = hi.v;
        if (lane == 0) g_zsq[gw] = s;
    } else {
        *(uint4*)(b_ext + (size_t)(gw - BT_) * K_EXT + lane * 8) = hi.v;
        if (lane == 0) g_bsq[gw - BT_] = s;
    }
}

// ---------------------------------------------------------------------------
// argmin over d[b,0,:]  (exact fp32)
// ---------------------------------------------------------------------------
__global__ void k_first(const float* __restrict__ z, const float* __restrict__ w) {
    int b = blockIdx.x;
    __shared__ __align__(16) float zs[E_];
    __shared__ float sd[8];
    __shared__ int   sn[8];
    int tid = threadIdx.x;
    zs[tid] = z[(size_t)b * T_ * E_ + tid];
    __syncthreads();

    float zsq0 = g_zsq[b * T_];
    int warp = tid >> 5, lane = tid & 31;
    float4 za = *(const float4*)(zs + 4 * lane);
    float4 zb = *(const float4*)(zs + 128 + 4 * lane);

    float best = 3.4e38f;
    int bestn = 0x7fffffff;
    for (int n = warp; n < NB_; n += 8) {
        const float* wr = w + (size_t)n * E_;
        float4 wa = *(const float4*)(wr + 4 * lane);
        float4 wb = *(const float4*)(wr + 128 + 4 * lane);
        float p = za.x * wa.x + za.y * wa.y + za.z * wa.z + za.w * wa.w
                + zb.x * wb.x + zb.y * wb.y + zb.z * wb.z + zb.w * wb.w;
        p = warp_sum(p);
        float d = (zsq0 + g_bsq[n]) - 2.0f * p;
        if (d < best || (d == best && n < bestn)) { best = d; bestn = n; }
    }
    if (lane == 0) { sd[warp] = best; sn[warp] = bestn; }
    __syncthreads();
    if (tid == 0) {
        float bd = sd[0]; int bn = sn[0];
        for (int j = 1; j < 8; j++)
            if (sd[j] < bd || (sd[j] == bd && sn[j] < bn)) { bd = sd[j]; bn = sn[j]; }
        g_ind[b * T_] = min(bn, NE_ - 1);
    }
}

// ---------------------------------------------------------------------------
// Mega kernel (128 threads/block).
// Blocks 0..15: trailing HYBRID scan — fp16-d decisions, exact fp32
// recompute when |margin| < THETA (rare, whole-warp-uniform).
// Blocks 16..: HMMA fp16 GEMM (K=256), warp tile 64x64, flag release.
// ---------------------------------------------------------------------------
__global__ void __launch_bounds__(128) k_mega(const float* __restrict__ zf,
                                              const float* __restrict__ wf) {
    __shared__ __align__(16) __half As[2][128][ASTRIDE];
    __shared__ __align__(16) __half Bs[2][128][ASTRIDE];

    int tid = threadIdx.x;

    if (blockIdx.x < 16) {
        // ---------------- scan path ----------------
        if (tid >= 32) return;
        int b = blockIdx.x;
        int lane = tid;
        int ibb = b * T_;
        int ia = g_ind[ibb];
        float coe = 0.0f;
        const float PC = 0.1f / 1024.0f;
        int pl = min(lane, 23);
        int ready_hi = 0;
        int* gout = g_ind + ibb;
        int* sink = &g_sink[b];

#define WAITROW(tt)                                                        \
        while ((tt) >= ready_hi) {                                         \
            int fidx = ((ready_hi >> 7) << 4) + b;                         \
            while (ld_acq(&g_rowflag[fidx]) < NTILES_N) __nanosleep(64);   \
            ready_hi += 128;                                               \
        }

        float wv[4][4];
        int bs0, bs1, bs2, bs3;

        WAITROW(16 <= T_ - 1 ? 16 : T_ - 1);
        int ab0 = ia & ~3;
#pragma unroll
        for (int s = 0; s < 4; ++s)
#pragma unroll
            for (int j = 0; j < 4; ++j)
                wv[s][j] = g_d[(size_t)(ibb + 1 + s * 4 + j) * DSTRIDE + ab0 + pl];
        bs0 = ab0; bs1 = ab0; bs2 = ab0; bs3 = ab0;

        int t = 1;
#define PROCG(S, BASEVAR)                                                  \
        {                                                                  \
            int base_ = BASEVAR;                                           \
            _Pragma("unroll")                                              \
            for (int j = 0; j < 4; ++j) {                                  \
                int ib2 = min(ia + 1, NE_ - 1);                            \
                float qh = __shfl_sync(0xffffffffu, wv[S][j], ia - base_); \
                float qn = __shfl_sync(0xffffffffu, wv[S][j], ib2 - base_);\
                float mar = qh - qn + coe;                                 \
                bool stay;                                                 \
                int tt = t + j;                                            \
                if (fabsf(mar) < THETA && tt <= T_ - 1) {                  \
                    const float* zr = zf + (size_t)(ibb + tt) * E_ + lane * 8; \
                    const float* wA = wf + (size_t)ia * E_ + lane * 8;     \
                    const float* wB = wf + (size_t)ib2 * E_ + lane * 8;    \
                    float dotA = 0.0f, dotB = 0.0f;                        \
                    _Pragma("unroll")                                      \
                    for (int e = 0; e < 8; e++) {                          \
                        float zv_ = zr[e];                                 \
                        dotA += zv_ * wA[e];                               \
                        dotB += zv_ * wB[e];                               \
                    }                                                      \
                    _Pragma("unroll")                                      \
                    for (int o = 16; o > 0; o >>= 1) {                     \
                        dotA += __shfl_xor_sync(0xffffffffu, dotA, o);     \
                        dotB += __shfl_xor_sync(0xffffffffu, dotB, o);     \
                    }                                                      \
                    float zst = g_zsq[ibb + tt];                           \
                    float dAe = (zst + g_bsq[ia]) - 2.0f * dotA;           \
                    float dBe = (zst + g_bsq[ib2]) - 2.0f * dotB;          \
                    stay = (dAe <= dBe - coe);                             \
                } else {                                                   \
                    stay = (mar <= 0.0f);                                  \
                }                                                          \
                ia  = stay ? ia : ib2;                                     \
                coe = stay ? coe + PC : 0.0f;                              \
                if (lane == 0) {                                           \
                    int* a_ = (tt <= T_ - 1) ? (gout + tt) : sink;         \
                    *a_ = ia;                                              \
                }                                                          \
            }                                                              \
            t += 4;                                                        \
            int tp = t + 12;                                               \
            if (tp + 3 <= T_) {                                            \
                int wr_ = tp + 3 <= T_ - 1 ? tp + 3 : T_ - 1;              \
                WAITROW(wr_);                                              \
                int ab_ = ia & ~3;                                         \
                _Pragma("unroll")                                          \
                for (int j = 0; j < 4; ++j)                                \
                    wv[S][j] = g_d[(size_t)(ibb + tp + j) * DSTRIDE + ab_ + pl]; \
                BASEVAR = ab_;                                             \
            }                                                              \
        }

#pragma unroll 1
        for (int it = 0; it < 64; ++it) {
            PROCG(0, bs0)
            PROCG(1, bs1)
            PROCG(2, bs2)
            PROCG(3, bs3)
        }
#undef PROCG
#undef WAITROW
        return;
    }

    // ---------------- GEMM path: 4 warps, warp tile 64x64 ----------------
    int wid = tid >> 5;
    int lane = tid & 31;
    int warp_m = wid >> 1;      // 0..1 -> 64-row slice
    int warp_n = wid & 1;       // 0..1 -> 64-col slice

    int gi = blockIdx.x - 16;
    int nt0 = gi % NTILES_N;
    int rb  = gi / NTILES_N;                 // rb = tc*16 + b
    int row0 = (rb & 15) * T_ + (rb >> 4) * 128;
    int n0   = nt0 * 128;

    float acc[4][8][4];
#pragma unroll
    for (int i = 0; i < 4; i++)
#pragma unroll
        for (int j = 0; j < 8; j++)
#pragma unroll
            for (int k = 0; k < 4; k++) acc[i][j][k] = 0.0f;

    uint32_t a_base = smem_u32(&As[0][0][0]);
    uint32_t b_base = smem_u32(&Bs[0][0][0]);
    const uint32_t STAGE_BYTES = 128 * ASTRIDE * 2;

    int lr_ = tid >> 2, seg = tid & 3;
    const __half* apz = a_ext + (size_t)(row0 + lr_) * K_EXT + seg * 8;
    const __half* bpz = b_ext + (size_t)(n0 + lr_) * K_EXT + seg * 8;
    uint32_t adst = a_base + lr_ * (ASTRIDE * 2) + seg * 16;
    uint32_t bdst = b_base + lr_ * (ASTRIDE * 2) + seg * 16;

#define LOADCH(c, buf)                                                       \
    {                                                                        \
        uint32_t so = (buf) * STAGE_BYTES;                                   \
        int ko = (c) * KCH;                                                  \
        _Pragma("unroll")                                                    \
        for (int i = 0; i < 4; i++) {                                        \
            CP16(adst + so + i * (32 * ASTRIDE * 2),                         \
                 (const char*)(apz + (size_t)i * 32 * K_EXT + ko));          \
            CP16(bdst + so + i * (32 * ASTRIDE * 2),                         \
                 (const char*)(bpz + (size_t)i * 32 * K_EXT + ko));          \
        }                                                                    \
        CPCOMMIT();                                                          \
    }

    LOADCH(0, 0);

    int lrow = lane & 15;
    int lcol8 = (lane >> 4) * 8;
    uint32_t a_lm = a_base + (warp_m * 64 + lrow) * (ASTRIDE * 2) + lcol8 * 2;
    uint32_t b_lm = b_base + (warp_n * 64 + lrow) * (ASTRIDE * 2) + lcol8 * 2;

#pragma unroll 1
    for (int c = 0; c < NCH; ++c) {
        int p = c & 1;
        if (c + 1 < NCH) {
            LOADCH(c + 1, 1 - p);
            CPWAIT(1);
        } else {
            CPWAIT(0);
        }
        __syncthreads();
        uint32_t so = p * STAGE_BYTES;
#pragma unroll
        for (int ks = 0; ks < 2; ks++) {
            unsigned af[4][4];
#pragma unroll
            for (int mt = 0; mt < 4; mt++)
                LDSM4(af[mt][0], af[mt][1], af[mt][2], af[mt][3],
                      a_lm + so + mt * 16 * (ASTRIDE * 2) + ks * 32);
            unsigned bf[4][4];
#pragma unroll
            for (int np = 0; np < 4; np++)
                LDSM4(bf[np][0], bf[np][1], bf[np][2], bf[np][3],
                      b_lm + so + np * 16 * (ASTRIDE * 2) + ks * 32);
#pragma unroll
            for (int mt = 0; mt < 4; mt++)
#pragma unroll
                for (int ntile = 0; ntile < 8; ntile++)
                    mma16816(acc[mt][ntile], af[mt],
                             bf[ntile >> 1][ntile & 1],
                             bf[ntile >> 1][(ntile & 1) + 2]);
        }
        __syncthreads();
    }

    // epilogue: d = (zsq + bsq) - 2*cross   (reference fp32 grid)
    int rbase = row0 + warp_m * 64;
    int cbase = n0 + warp_n * 64;
    int rlo = rbase + (lane >> 2);
    int csub = (lane & 3) * 2;
#pragma unroll
    for (int mt = 0; mt < 4; mt++) {
        int r0 = rlo + mt * 16;
        int r1 = r0 + 8;
        float zs0 = g_zsq[r0], zs1 = g_zsq[r1];
        float* dp0 = g_d + (size_t)r0 * DSTRIDE;
        float* dp1 = g_d + (size_t)r1 * DSTRIDE;
#pragma unroll
        for (int ntile = 0; ntile < 8; ntile++) {
            int col = cbase + ntile * 8 + csub;
            float b0 = g_bsq[col], b1 = g_bsq[col + 1];
            float2 v0, v1;
            v0.x = (zs0 + b0) - 2.0f * acc[mt][ntile][0];
            v0.y = (zs0 + b1) - 2.0f * acc[mt][ntile][1];
            v1.x = (zs1 + b0) - 2.0f * acc[mt][ntile][2];
            v1.y = (zs1 + b1) - 2.0f * acc[mt][ntile][3];
            *(float2*)(dp0 + col) = v0;
            *(float2*)(dp1 + col) = v1;
        }
    }

    // release this tile for the scan (generic proxy: fence + relaxed atomic)
    __threadfence();
    __syncthreads();
    if (tid == 0) atomicAdd(&g_rowflag[rb], 1);
#undef LOADCH
}

// ---------------------------------------------------------------------------
// k_post: gather z_q + indices + li, relu-sum loss over d rows (cols 0..1023)
// plus inline column 1024 (dot with book row 1024).
// ---------------------------------------------------------------------------
__global__ void __launch_bounds__(256) k_post(const float* __restrict__ z,
                                              const float* __restrict__ w,
                                              float* __restrict__ out,
                                              long long out_size) {
    __shared__ double wpart[8];
    int warp = threadIdx.x >> 5;
    int lane = threadIdx.x & 31;
    int row = blockIdx.x * 8 + warp;

    int idx = g_ind[row];
    const float* br = w + (size_t)idx * E_;
    const float* zrow = z + (size_t)row * E_;
    const float* wl = w + (size_t)NE_ * E_;      // book row 1024
    bool wz = (out_size >= (long long)ZQ_SIZE);

    float li = 0.0f, dq = 0.0f;
#pragma unroll
    for (int h = 0; h < 2; h++) {
        int off = h * 128 + 4 * lane;
        float4 q  = *(const float4*)(br + off);
        float4 zv = *(const float4*)(zrow + off);
        float4 wv = *(const float4*)(wl + off);
        float4 o;
        o.x = zv.x + (q.x - zv.x);
        o.y = zv.y + (q.y - zv.y);
        o.z = zv.z + (q.z - zv.z);
        o.w = zv.w + (q.w - zv.w);
        float dx = zv.x - q.x; li += dx * dx;
        dx = zv.y - q.y; li += dx * dx;
        dx = zv.z - q.z; li += dx * dx;
        dx = zv.w - q.w; li += dx * dx;
        dq += zv.x * wv.x + zv.y * wv.y + zv.z * wv.z + zv.w * wv.w;
        if (wz) *(float4*)(out + (size_t)row * E_ + off) = o;
    }
    li = warp_sum(li);
    dq = warp_sum(dq);
    li = __shfl_sync(0xffffffffu, li, 0);
    if (lane == 0 && out_size >= (long long)(IND_OFF + BT_))
        out[IND_OFF + row] = (float)idx;

    const float EPS_ = 1e-6f / 1024.0f;
    const float* drow = g_d + (size_t)row * DSTRIDE;
    float s = 0.0f;
#pragma unroll
    for (int m = 0; m < 8; m++) {
        float4 dv = *(const float4*)(drow + m * 128 + 4 * lane);
        s += fmaxf((li - dv.x) + EPS_, 0.0f);
        s += fmaxf((li - dv.y) + EPS_, 0.0f);
        s += fmaxf((li - dv.z) + EPS_, 0.0f);
        s += fmaxf((li - dv.w) + EPS_, 0.0f);
    }
    if (lane == 0) {
        float d1024 = (g_zsq[row] + g_bsq[NE_]) - 2.0f * dq;
        s += fmaxf((li - d1024) + EPS_, 0.0f);
    }
    s = warp_sum(s);
    if (lane == 0) wpart[warp] = (double)s;
    __syncthreads();
    if (threadIdx.x == 0) {
        double t = 0.0;
        for (int j = 0; j < 8; j++) t += wpart[j];
        g_part[blockIdx.x] = t;
    }
}

// ---------------------------------------------------------------------------
__global__ void k_final(float* __restrict__ out, long long out_size) {
    __shared__ double sd[256];
    __shared__ int smn[256], smx[256];
    int tid = threadIdx.x;
    double s = 0.0;
    for (int i = tid; i < NPOST; i += 256) s += g_part[i];
    int mn = 0x7fffffff, mx = -0x7fffffff;
    for (int i = tid; i < BT_; i += 256) {
        int v = g_ind[i];
        mn = min(mn, v);
        mx = max(mx, v);
    }
    sd[tid] = s; smn[tid] = mn; smx[tid] = mx;
    __syncthreads();
    for (int st = 128; st > 0; st >>= 1) {
        if (tid < st) {
            sd[tid] += sd[tid + st];
            smn[tid] = min(smn[tid], smn[tid + st]);
            smx[tid] = max(smx[tid], smx[tid + st]);
        }
        __syncthreads();
    }
    if (tid == 0) {
        float m = (float)(sd[0] / ((double)BT_ * (double)NB_));
        float loss = 0.25f * m + m;
        if (out_size > (long long)LOSS_OFF) out[LOSS_OFF] = loss;
        if (out_size > (long long)V_OFF)    out[V_OFF] = (float)(smx[0] - smn[0]);
    }
}

// ---------------------------------------------------------------------------
extern "C" void kernel_launch(void* const* d_in, const int* in_sizes, int n_in,
                              void* d_out, int out_size) {
    const float* z = (const float*)d_in[0];
    const float* w = (const float*)d_in[1];
    if (n_in >= 2 && in_sizes[0] == NB_ * E_ && in_sizes[1] == BT_ * E_) {
        const float* tmp = z; z = w; w = tmp;
    }
    float* out = (float*)d_out;
    long long osz = (long long)out_size;

    k_prep<<<(BT_ + NB_ + 7) / 8, 256>>>(z, w);
    k_first<<<B_, 256>>>(z, w);
    k_mega<<<16 + NGEMM, 128>>>(z, w);
    k_post<<<NPOST, 256>>>(z, w, out, osz);
    k_final<<<1, 256>>>(out, osz);
}

// round 15
// speedup vs baseline: 3.5080x; 3.5080x over previous
#include <cuda_runtime.h>
#include <cuda_fp16.h>
#include <cstdint>

#define B_   16
#define T_   1024
#define E_   256
#define NB_  1025
#define BT_  16384
#define NE_  1024

#define ZQ_SIZE  (BT_ * E_)
#define LOSS_OFF ZQ_SIZE
#define IND_OFF  (ZQ_SIZE + 1)
#define V_OFF    (IND_OFF + BT_)

#define DSTRIDE  1024
#define NTILES_N 8               // 8 * 128 = 1024 cols (col 1024 handled in k_post)
#define NTILES_R 128             // 128-row chunks, t-chunk-major: rb = tc*16 + b
#define NGEMM    (NTILES_N * NTILES_R)
#define NPOST    2048

#define K_EXT    256             // plain fp16 GEMM + hybrid-precision scan
#define KCH      32
#define NCH      (K_EXT / KCH)   // 8
#define ASTRIDE  40              // half elements per smem row (80 B)

#define THETA    2e-4f           // scan recompute trigger (interior near-ties only)

typedef unsigned long long ull;

__device__ int    g_ind[BT_];
__device__ int    g_sink[B_];
__device__ float  g_zsq[BT_];
__device__ float  g_bsq[1152];
__device__ float  g_d[(size_t)(BT_ + 16) * DSTRIDE];   // padded rows for scan tail
__device__ double g_part[NPOST];
__device__ int    g_rowflag[NTILES_R];
__device__ __half a_ext[(size_t)BT_ * K_EXT];   // 8 MB
__device__ __half b_ext[(size_t)NB_ * K_EXT];   // 0.5 MB

static __device__ __forceinline__ float warp_sum(float v) {
#pragma unroll
    for (int o = 16; o > 0; o >>= 1) v += __shfl_xor_sync(0xffffffffu, v, o);
    return v;
}

static __device__ __forceinline__ uint32_t smem_u32(const void* p) {
    uint32_t a;
    asm("{ .reg .u64 t; cvta.to.shared.u64 t, %1; cvt.u32.u64 %0, t; }"
        : "=r"(a) : "l"(p));
    return a;
}

static __device__ __forceinline__ int ld_acq(const int* p) {
    int v;
    asm volatile("ld.acquire.gpu.global.s32 %0, [%1];" : "=r"(v) : "l"(p) : "memory");
    return v;
}

#define CP16(dst, src) \
    asm volatile("cp.async.cg.shared.global [%0], [%1], 16;" :: "r"(dst), "l"(src))
#define CPCOMMIT() asm volatile("cp.async.commit_group;" ::: "memory")
#define CPWAIT(N)  asm volatile("cp.async.wait_group %0;" :: "n"(N) : "memory")

#define LDSM4(r0, r1, r2, r3, addr) \
    asm volatile("ldmatrix.sync.aligned.m8n8.x4.shared.b16 {%0,%1,%2,%3}, [%4];" \
                 : "=r"(r0), "=r"(r1), "=r"(r2), "=r"(r3) : "r"(addr))

static __device__ __forceinline__ void mma16816(float* c, const unsigned* a,
                                                unsigned b0, unsigned b1) {
    asm volatile(
        "mma.sync.aligned.m16n8k16.row.col.f32.f16.f16.f32 "
        "{%0,%1,%2,%3}, {%4,%5,%6,%7}, {%8,%9}, {%0,%1,%2,%3};"
        : "+f"(c[0]), "+f"(c[1]), "+f"(c[2]), "+f"(c[3])
        : "r"(a[0]), "r"(a[1]), "r"(a[2]), "r"(a[3]), "r"(b0), "r"(b1));
}

// ---------------------------------------------------------------------------
// k_prep: fused row norms + fp16 convert + flag reset.
// ---------------------------------------------------------------------------
__global__ void k_prep(const float* __restrict__ z, const float* __restrict__ w) {
    if (blockIdx.x == 0 && threadIdx.x < NTILES_R) g_rowflag[threadIdx.x] = 0;
    int gw = (blockIdx.x * blockDim.x + threadIdx.x) >> 5;
    int lane = threadIdx.x & 31;
    if (gw >= BT_ + NB_) return;

    const float* src = (gw < BT_) ? (z + (size_t)gw * E_ + lane * 8)
                                  : (w + (size_t)(gw - BT_) * E_ + lane * 8);
    float4 a = *(const float4*)src;
    float4 b = *(const float4*)(src + 4);
    float f[8] = {a.x, a.y, a.z, a.w, b.x, b.y, b.z, b.w};

    float s = 0.0f;
    union { __half h[8]; uint4 v; } hi;
#pragma unroll
    for (int j = 0; j < 8; j++) {
        s += f[j] * f[j];
        hi.h[j] = __float2half_rn(f[j]);
    }
    s = warp_sum(s);

    if (gw < BT_) {
        *(uint4*)(a_ext + (size_t)gw * K_EXT + lane * 8) = hi.v;
        if (lane == 0) g_zsq[gw] = s;
    } else {
        *(uint4*)(b_ext + (size_t)(gw - BT_) * K_EXT + lane * 8) = hi.v;
        if (lane == 0) g_bsq[gw - BT_] = s;
    }
}

// ---------------------------------------------------------------------------
// argmin over d[b,0,:]  (exact fp32)
// ---------------------------------------------------------------------------
__global__ void k_first(const float* __restrict__ z, const float* __restrict__ w) {
    int b = blockIdx.x;
    __shared__ __align__(16) float zs[E_];
    __shared__ float sd[8];
    __shared__ int   sn[8];
    int tid = threadIdx.x;
    zs[tid] = z[(size_t)b * T_ * E_ + tid];
    __syncthreads();

    float zsq0 = g_zsq[b * T_];
    int warp = tid >> 5, lane = tid & 31;
    float4 za = *(const float4*)(zs + 4 * lane);
    float4 zb = *(const float4*)(zs + 128 + 4 * lane);

    float best = 3.4e38f;
    int bestn = 0x7fffffff;
    for (int n = warp; n < NB_; n += 8) {
        const float* wr = w + (size_t)n * E_;
        float4 wa = *(const float4*)(wr + 4 * lane);
        float4 wb = *(const float4*)(wr + 128 + 4 * lane);
        float p = za.x * wa.x + za.y * wa.y + za.z * wa.z + za.w * wa.w
                + zb.x * wb.x + zb.y * wb.y + zb.z * wb.z + zb.w * wb.w;
        p = warp_sum(p);
        float d = (zsq0 + g_bsq[n]) - 2.0f * p;
        if (d < best || (d == best && n < bestn)) { best = d; bestn = n; }
    }
    if (lane == 0) { sd[warp] = best; sn[warp] = bestn; }
    __syncthreads();
    if (tid == 0) {
        float bd = sd[0]; int bn = sn[0];
        for (int j = 1; j < 8; j++)
            if (sd[j] < bd || (sd[j] == bd && sn[j] < bn)) { bd = sd[j]; bn = sn[j]; }
        g_ind[b * T_] = min(bn, NE_ - 1);
    }
}

// ---------------------------------------------------------------------------
// Mega kernel (128 threads/block).
// Blocks 0..15: trailing HYBRID scan — fp16-d decisions; exact fp32 recompute
// ONLY on interior near-ties (ia != ib2). At the ia==ib2 boundary the fp16
// comparison is bit-exact (same value both sides), so no recompute there.
// Blocks 16..: HMMA fp16 GEMM (K=256), warp tile 64x64, flag release.
// ---------------------------------------------------------------------------
__global__ void __launch_bounds__(128) k_mega(const float* __restrict__ zf,
                                              const float* __restrict__ wf) {
    __shared__ __align__(16) __half As[2][128][ASTRIDE];
    __shared__ __align__(16) __half Bs[2][128][ASTRIDE];

    int tid = threadIdx.x;

    if (blockIdx.x < 16) {
        // ---------------- scan path ----------------
        if (tid >= 32) return;
        int b = blockIdx.x;
        int lane = tid;
        int ibb = b * T_;
        int ia = g_ind[ibb];
        float coe = 0.0f;
        const float PC = 0.1f / 1024.0f;
        int pl = min(lane, 23);
        int ready_hi = 0;
        int* gout = g_ind + ibb;
        int* sink = &g_sink[b];

#define WAITROW(tt)                                                        \
        while ((tt) >= ready_hi) {                                         \
            int fidx = ((ready_hi >> 7) << 4) + b;                         \
            while (ld_acq(&g_rowflag[fidx]) < NTILES_N) __nanosleep(64);   \
            ready_hi += 128;                                               \
        }

        float wv[4][4];
        int bs0, bs1, bs2, bs3;

        WAITROW(16 <= T_ - 1 ? 16 : T_ - 1);
        int ab0 = ia & ~3;
#pragma unroll
        for (int s = 0; s < 4; ++s)
#pragma unroll
            for (int j = 0; j < 4; ++j)
                wv[s][j] = g_d[(size_t)(ibb + 1 + s * 4 + j) * DSTRIDE + ab0 + pl];
        bs0 = ab0; bs1 = ab0; bs2 = ab0; bs3 = ab0;

        int t = 1;
#define PROCG(S, BASEVAR)                                                  \
        {                                                                  \
            int base_ = BASEVAR;                                           \
            _Pragma("unroll")                                              \
            for (int j = 0; j < 4; ++j) {                                  \
                int ib2 = min(ia + 1, NE_ - 1);                            \
                float qh = __shfl_sync(0xffffffffu, wv[S][j], ia - base_); \
                float qn = __shfl_sync(0xffffffffu, wv[S][j], ib2 - base_);\
                float mar = qh - qn + coe;                                 \
                bool stay;                                                 \
                int tt = t + j;                                            \
                if (fabsf(mar) < THETA && ia != ib2 && tt <= T_ - 1) {     \
                    const float* zr = zf + (size_t)(ibb + tt) * E_ + lane * 8; \
                    const float* wA = wf + (size_t)ia * E_ + lane * 8;     \
                    const float* wB = wf + (size_t)ib2 * E_ + lane * 8;    \
                    float dotA = 0.0f, dotB = 0.0f;                        \
                    _Pragma("unroll")                                      \
                    for (int e = 0; e < 8; e++) {                          \
                        float zv_ = zr[e];                                 \
                        dotA += zv_ * wA[e];                               \
                        dotB += zv_ * wB[e];                               \
                    }                                                      \
                    _Pragma("unroll")                                      \
                    for (int o = 16; o > 0; o >>= 1) {                     \
                        dotA += __shfl_xor_sync(0xffffffffu, dotA, o);     \
                        dotB += __shfl_xor_sync(0xffffffffu, dotB, o);     \
                    }                                                      \
                    float zst = g_zsq[ibb + tt];                           \
                    float dAe = (zst + g_bsq[ia]) - 2.0f * dotA;           \
                    float dBe = (zst + g_bsq[ib2]) - 2.0f * dotB;          \
                    stay = (dAe <= dBe - coe);                             \
                } else {                                                   \
                    stay = (mar <= 0.0f);                                  \
                }                                                          \
                ia  = stay ? ia : ib2;                                     \
                coe = stay ? coe + PC : 0.0f;                              \
                if (lane == 0) {                                           \
                    int* a_ = (tt <= T_ - 1) ? (gout + tt) : sink;         \
                    *a_ = ia;                                              \
                }                                                          \
            }                                                              \
            t += 4;                                                        \
            int tp = t + 12;                                               \
            if (tp + 3 <= T_) {                                            \
                int wr_ = tp + 3 <= T_ - 1 ? tp + 3 : T_ - 1;              \
                WAITROW(wr_);                                              \
                int ab_ = ia & ~3;                                         \
                _Pragma("unroll")                                          \
                for (int j = 0; j < 4; ++j)                                \
                    wv[S][j] = g_d[(size_t)(ibb + tp + j) * DSTRIDE + ab_ + pl]; \
                BASEVAR = ab_;                                             \
            }                                                              \
        }

#pragma unroll 1
        for (int it = 0; it < 64; ++it) {
            PROCG(0, bs0)
            PROCG(1, bs1)
            PROCG(2, bs2)
            PROCG(3, bs3)
        }
#undef PROCG
#undef WAITROW
        return;
    }

    // ---------------- GEMM path: 4 warps, warp tile 64x64 ----------------
    int wid = tid >> 5;
    int lane = tid & 31;
    int warp_m = wid >> 1;      // 0..1 -> 64-row slice
    int warp_n = wid & 1;       // 0..1 -> 64-col slice

    int gi = blockIdx.x - 16;
    int nt0 = gi % NTILES_N;
    int rb  = gi / NTILES_N;                 // rb = tc*16 + b
    int row0 = (rb & 15) * T_ + (rb >> 4) * 128;
    int n0   = nt0 * 128;

    float acc[4][8][4];
#pragma unroll
    for (int i = 0; i < 4; i++)
#pragma unroll
        for (int j = 0; j < 8; j++)
#pragma unroll
            for (int k = 0; k < 4; k++) acc[i][j][k] = 0.0f;

    uint32_t a_base = smem_u32(&As[0][0][0]);
    uint32_t b_base = smem_u32(&Bs[0][0][0]);
    const uint32_t STAGE_BYTES = 128 * ASTRIDE * 2;

    int lr_ = tid >> 2, seg = tid & 3;
    const __half* apz = a_ext + (size_t)(row0 + lr_) * K_EXT + seg * 8;
    const __half* bpz = b_ext + (size_t)(n0 + lr_) * K_EXT + seg * 8;
    uint32_t adst = a_base + lr_ * (ASTRIDE * 2) + seg * 16;
    uint32_t bdst = b_base + lr_ * (ASTRIDE * 2) + seg * 16;

#define LOADCH(c, buf)                                                       \
    {                                                                        \
        uint32_t so = (buf) * STAGE_BYTES;                                   \
        int ko = (c) * KCH;                                                  \
        _Pragma("unroll")                                                    \
        for (int i = 0; i < 4; i++) {                                        \
            CP16(adst + so + i * (32 * ASTRIDE * 2),                         \
                 (const char*)(apz + (size_t)i * 32 * K_EXT + ko));          \
            CP16(bdst + so + i * (32 * ASTRIDE * 2),                         \
                 (const char*)(bpz + (size_t)i * 32 * K_EXT + ko));          \
        }                                                                    \
        CPCOMMIT();                                                          \
    }

    LOADCH(0, 0);

    int lrow = lane & 15;
    int lcol8 = (lane >> 4) * 8;
    uint32_t a_lm = a_base + (warp_m * 64 + lrow) * (ASTRIDE * 2) + lcol8 * 2;
    uint32_t b_lm = b_base + (warp_n * 64 + lrow) * (ASTRIDE * 2) + lcol8 * 2;

#pragma unroll 1
    for (int c = 0; c < NCH; ++c) {
        int p = c & 1;
        if (c + 1 < NCH) {
            LOADCH(c + 1, 1 - p);
            CPWAIT(1);
        } else {
            CPWAIT(0);
        }
        __syncthreads();
        uint32_t so = p * STAGE_BYTES;
#pragma unroll
        for (int ks = 0; ks < 2; ks++) {
            unsigned af[4][4];
#pragma unroll
            for (int mt = 0; mt < 4; mt++)
                LDSM4(af[mt][0], af[mt][1], af[mt][2], af[mt][3],
                      a_lm + so + mt * 16 * (ASTRIDE * 2) + ks * 32);
            unsigned bf[4][4];
#pragma unroll
            for (int np = 0; np < 4; np++)
                LDSM4(bf[np][0], bf[np][1], bf[np][2], bf[np][3],
                      b_lm + so + np * 16 * (ASTRIDE * 2) + ks * 32);
#pragma unroll
            for (int mt = 0; mt < 4; mt++)
#pragma unroll
                for (int ntile = 0; ntile < 8; ntile++)
                    mma16816(acc[mt][ntile], af[mt],
                             bf[ntile >> 1][ntile & 1],
                             bf[ntile >> 1][(ntile & 1) + 2]);
        }
        __syncthreads();
    }

    // epilogue: d = (zsq + bsq) - 2*cross   (reference fp32 grid)
    int rbase = row0 + warp_m * 64;
    int cbase = n0 + warp_n * 64;
    int rlo = rbase + (lane >> 2);
    int csub = (lane & 3) * 2;
#pragma unroll
    for (int mt = 0; mt < 4; mt++) {
        int r0 = rlo + mt * 16;
        int r1 = r0 + 8;
        float zs0 = g_zsq[r0], zs1 = g_zsq[r1];
        float* dp0 = g_d + (size_t)r0 * DSTRIDE;
        float* dp1 = g_d + (size_t)r1 * DSTRIDE;
#pragma unroll
        for (int ntile = 0; ntile < 8; ntile++) {
            int col = cbase + ntile * 8 + csub;
            float b0 = g_bsq[col], b1 = g_bsq[col + 1];
            float2 v0, v1;
            v0.x = (zs0 + b0) - 2.0f * acc[mt][ntile][0];
            v0.y = (zs0 + b1) - 2.0f * acc[mt][ntile][1];
            v1.x = (zs1 + b0) - 2.0f * acc[mt][ntile][2];
            v1.y = (zs1 + b1) - 2.0f * acc[mt][ntile][3];
            *(float2*)(dp0 + col) = v0;
            *(float2*)(dp1 + col) = v1;
        }
    }

    // release this tile for the scan (generic proxy: fence + relaxed atomic)
    __threadfence();
    __syncthreads();
    if (tid == 0) atomicAdd(&g_rowflag[rb], 1);
#undef LOADCH
}

// ---------------------------------------------------------------------------
// k_post: gather z_q + indices + li, relu-sum loss over d rows (cols 0..1023)
// plus inline column 1024 (dot with book row 1024).
// ---------------------------------------------------------------------------
__global__ void __launch_bounds__(256) k_post(const float* __restrict__ z,
                                              const float* __restrict__ w,
                                              float* __restrict__ out,
                                              long long out_size) {
    __shared__ double wpart[8];
    int warp = threadIdx.x >> 5;
    int lane = threadIdx.x & 31;
    int row = blockIdx.x * 8 + warp;

    int idx = g_ind[row];
    const float* br = w + (size_t)idx * E_;
    const float* zrow = z + (size_t)row * E_;
    const float* wl = w + (size_t)NE_ * E_;      // book row 1024
    bool wz = (out_size >= (long long)ZQ_SIZE);

    float li = 0.0f, dq = 0.0f;
#pragma unroll
    for (int h = 0; h < 2; h++) {
        int off = h * 128 + 4 * lane;
        float4 q  = *(const float4*)(br + off);
        float4 zv = *(const float4*)(zrow + off);
        float4 wv = *(const float4*)(wl + off);
        float4 o;
        o.x = zv.x + (q.x - zv.x);
        o.y = zv.y + (q.y - zv.y);
        o.z = zv.z + (q.z - zv.z);
        o.w = zv.w + (q.w - zv.w);
        float dx = zv.x - q.x; li += dx * dx;
        dx = zv.y - q.y; li += dx * dx;
        dx = zv.z - q.z; li += dx * dx;
        dx = zv.w - q.w; li += dx * dx;
        dq += zv.x * wv.x + zv.y * wv.y + zv.z * wv.z + zv.w * wv.w;
        if (wz) *(float4*)(out + (size_t)row * E_ + off) = o;
    }
    li = warp_sum(li);
    dq = warp_sum(dq);
    li = __shfl_sync(0xffffffffu, li, 0);
    if (lane == 0 && out_size >= (long long)(IND_OFF + BT_))
        out[IND_OFF + row] = (float)idx;

    const float EPS_ = 1e-6f / 1024.0f;
    const float* drow = g_d + (size_t)row * DSTRIDE;
    float s = 0.0f;
#pragma unroll
    for (int m = 0; m < 8; m++) {
        float4 dv = *(const float4*)(drow + m * 128 + 4 * lane);
        s += fmaxf((li - dv.x) + EPS_, 0.0f);
        s += fmaxf((li - dv.y) + EPS_, 0.0f);
        s += fmaxf((li - dv.z) + EPS_, 0.0f);
        s += fmaxf((li - dv.w) + EPS_, 0.0f);
    }
    if (lane == 0) {
        float d1024 = (g_zsq[row] + g_bsq[NE_]) - 2.0f * dq;
        s += fmaxf((li - d1024) + EPS_, 0.0f);
    }
    s = warp_sum(s);
    if (lane == 0) wpart[warp] = (double)s;
    __syncthreads();
    if (threadIdx.x == 0) {
        double t = 0.0;
        for (int j = 0; j < 8; j++) t += wpart[j];
        g_part[blockIdx.x] = t;
    }
}

// ---------------------------------------------------------------------------
__global__ void k_final(float* __restrict__ out, long long out_size) {
    __shared__ double sd[256];
    __shared__ int smn[256], smx[256];
    int tid = threadIdx.x;
    double s = 0.0;
    for (int i = tid; i < NPOST; i += 256) s += g_part[i];
    int mn = 0x7fffffff, mx = -0x7fffffff;
    for (int i = tid; i < BT_; i += 256) {
        int v = g_ind[i];
        mn = min(mn, v);
        mx = max(mx, v);
    }
    sd[tid] = s; smn[tid] = mn; smx[tid] = mx;
    __syncthreads();
    for (int st = 128; st > 0; st >>= 1) {
        if (tid < st) {
            sd[tid] += sd[tid + st];
            smn[tid] = min(smn[tid], smn[tid + st]);
            smx[tid] = max(smx[tid], smx[tid + st]);
        }
        __syncthreads();
    }
    if (tid == 0) {
        float m = (float)(sd[0] / ((double)BT_ * (double)NB_));
        float loss = 0.25f * m + m;
        if (out_size > (long long)LOSS_OFF) out[LOSS_OFF] = loss;
        if (out_size > (long long)V_OFF)    out[V_OFF] = (float)(smx[0] - smn[0]);
    }
}

// ---------------------------------------------------------------------------
extern "C" void kernel_launch(void* const* d_in, const int* in_sizes, int n_in,
                              void* d_out, int out_size) {
    const float* z = (const float*)d_in[0];
    const float* w = (const float*)d_in[1];
    if (n_in >= 2 && in_sizes[0] == NB_ * E_ && in_sizes[1] == BT_ * E_) {
        const float* tmp = z; z = w; w = tmp;
    }
    float* out = (float*)d_out;
    long long osz = (long long)out_size;

    k_prep<<<(BT_ + NB_ + 7) / 8, 256>>>(z, w);
    k_first<<<B_, 256>>>(z, w);
    k_mega<<<16 + NGEMM, 128>>>(z, w);
    k_post<<<NPOST, 256>>>(z, w, out, osz);
    k_final<<<1, 256>>>(out, osz);
}

// round 16
// speedup vs baseline: 3.7374x; 1.0654x over previous
#include <cuda_runtime.h>
#include <cuda_fp16.h>
#include <cstdint>

#define B_   16
#define T_   1024
#define E_   256
#define NB_  1025
#define BT_  16384
#define NE_  1024

#define ZQ_SIZE  (BT_ * E_)
#define LOSS_OFF ZQ_SIZE
#define IND_OFF  (ZQ_SIZE + 1)
#define V_OFF    (IND_OFF + BT_)

#define DSTRIDE  1024
#define NTILES_N 8               // 8 * 128 = 1024 cols (col 1024 handled in k_post)
#define NTILES_R 128
#define NGEMM    (NTILES_N * NTILES_R)   // 1024
#define NPOST    2048

#define K_EXT    256             // plain fp16 GEMM + hybrid-precision scan
#define KCH      32
#define NCH      (K_EXT / KCH)   // 8
#define ASTRIDE  40              // half elements per smem row (80 B)

#define THETA    2e-4f           // recompute trigger (interior near-ties only)

typedef unsigned long long ull;

__device__ int    g_ind[BT_];
__device__ int    g_sink[B_];
__device__ float  g_zsq[BT_];
__device__ float  g_bsq[1152];
__device__ float  g_d[(size_t)(BT_ + 16) * DSTRIDE];   // padded rows for scan tail
__device__ double g_part[NPOST];
__device__ __half a_ext[(size_t)BT_ * K_EXT];   // 8 MB
__device__ __half b_ext[(size_t)NB_ * K_EXT];   // 0.5 MB

static __device__ __forceinline__ float warp_sum(float v) {
#pragma unroll
    for (int o = 16; o > 0; o >>= 1) v += __shfl_xor_sync(0xffffffffu, v, o);
    return v;
}

static __device__ __forceinline__ uint32_t smem_u32(const void* p) {
    uint32_t a;
    asm("{ .reg .u64 t; cvta.to.shared.u64 t, %1; cvt.u32.u64 %0, t; }"
        : "=r"(a) : "l"(p));
    return a;
}

static __device__ __forceinline__ float lds_f(uint32_t addr) {
    float v;
    asm volatile("ld.shared.f32 %0, [%1];" : "=f"(v) : "r"(addr));
    return v;
}

#define CP16(dst, src) \
    asm volatile("cp.async.cg.shared.global [%0], [%1], 16;" :: "r"(dst), "l"(src))
#define CP16S(dst, src, sz) \
    asm volatile("cp.async.cg.shared.global [%0], [%1], 16, %2;" :: "r"(dst), "l"(src), "r"(sz))
#define CPCOMMIT() asm volatile("cp.async.commit_group;" ::: "memory")
#define CPWAIT(N)  asm volatile("cp.async.wait_group %0;" :: "n"(N) : "memory")

#define LDSM4(r0, r1, r2, r3, addr) \
    asm volatile("ldmatrix.sync.aligned.m8n8.x4.shared.b16 {%0,%1,%2,%3}, [%4];" \
                 : "=r"(r0), "=r"(r1), "=r"(r2), "=r"(r3) : "r"(addr))

static __device__ __forceinline__ void mma16816(float* c, const unsigned* a,
                                                unsigned b0, unsigned b1) {
    asm volatile(
        "mma.sync.aligned.m16n8k16.row.col.f32.f16.f16.f32 "
        "{%0,%1,%2,%3}, {%4,%5,%6,%7}, {%8,%9}, {%0,%1,%2,%3};"
        : "+f"(c[0]), "+f"(c[1]), "+f"(c[2]), "+f"(c[3])
        : "r"(a[0]), "r"(a[1]), "r"(a[2]), "r"(a[3]), "r"(b0), "r"(b1));
}

// ---------------------------------------------------------------------------
// k_prep: fused row norms + fp16 convert.
// ---------------------------------------------------------------------------
__global__ void k_prep(const float* __restrict__ z, const float* __restrict__ w) {
    int gw = (blockIdx.x * blockDim.x + threadIdx.x) >> 5;
    int lane = threadIdx.x & 31;
    if (gw >= BT_ + NB_) return;

    const float* src = (gw < BT_) ? (z + (size_t)gw * E_ + lane * 8)
                                  : (w + (size_t)(gw - BT_) * E_ + lane * 8);
    float4 a = *(const float4*)src;
    float4 b = *(const float4*)(src + 4);
    float f[8] = {a.x, a.y, a.z, a.w, b.x, b.y, b.z, b.w};

    float s = 0.0f;
    union { __half h[8]; uint4 v; } hi;
#pragma unroll
    for (int j = 0; j < 8; j++) {
        s += f[j] * f[j];
        hi.h[j] = __float2half_rn(f[j]);
    }
    s = warp_sum(s);

    if (gw < BT_) {
        *(uint4*)(a_ext + (size_t)gw * K_EXT + lane * 8) = hi.v;
        if (lane == 0) g_zsq[gw] = s;
    } else {
        *(uint4*)(b_ext + (size_t)(gw - BT_) * K_EXT + lane * 8) = hi.v;
        if (lane == 0) g_bsq[gw - BT_] = s;
    }
}

// ---------------------------------------------------------------------------
// argmin over d[b,0,:]  (exact fp32)
// ---------------------------------------------------------------------------
__global__ void k_first(const float* __restrict__ z, const float* __restrict__ w) {
    int b = blockIdx.x;
    __shared__ __align__(16) float zs[E_];
    __shared__ float sd[8];
    __shared__ int   sn[8];
    int tid = threadIdx.x;
    zs[tid] = z[(size_t)b * T_ * E_ + tid];
    __syncthreads();

    float zsq0 = g_zsq[b * T_];
    int warp = tid >> 5, lane = tid & 31;
    float4 za = *(const float4*)(zs + 4 * lane);
    float4 zb = *(const float4*)(zs + 128 + 4 * lane);

    float best = 3.4e38f;
    int bestn = 0x7fffffff;
    for (int n = warp; n < NB_; n += 8) {
        const float* wr = w + (size_t)n * E_;
        float4 wa = *(const float4*)(wr + 4 * lane);
        float4 wb = *(const float4*)(wr + 128 + 4 * lane);
        float p = za.x * wa.x + za.y * wa.y + za.z * wa.z + za.w * wa.w
                + zb.x * wb.x + zb.y * wb.y + zb.z * wb.z + zb.w * wb.w;
        p = warp_sum(p);
        float d = (zsq0 + g_bsq[n]) - 2.0f * p;
        if (d < best || (d == best && n < bestn)) { best = d; bestn = n; }
    }
    if (lane == 0) { sd[warp] = best; sn[warp] = bestn; }
    __syncthreads();
    if (tid == 0) {
        float bd = sd[0]; int bn = sn[0];
        for (int j = 1; j < 8; j++)
            if (sd[j] < bd || (sd[j] == bd && sn[j] < bn)) { bd = sd[j]; bn = sn[j]; }
        g_ind[b * T_] = min(bn, NE_ - 1);
    }
}

// ---------------------------------------------------------------------------
// fp16 GEMM via mma.sync: CTA 128x128, warp tile 64x64 (4 warps), K=256,
// double-buffered cp.async. d = (zsq + bsq) - 2*cross -> g_d.
// ---------------------------------------------------------------------------
__global__ void __launch_bounds__(128) k_gemm() {
    __shared__ __align__(16) __half As[2][128][ASTRIDE];
    __shared__ __align__(16) __half Bs[2][128][ASTRIDE];

    int tid = threadIdx.x;
    int wid = tid >> 5;
    int lane = tid & 31;
    int warp_m = wid >> 1;
    int warp_n = wid & 1;

    int bid = blockIdx.x;
    int nt0 = bid % NTILES_N;
    int rt  = bid / NTILES_N;
    int row0 = rt * 128;
    int n0   = nt0 * 128;

    float acc[4][8][4];
#pragma unroll
    for (int i = 0; i < 4; i++)
#pragma unroll
        for (int j = 0; j < 8; j++)
#pragma unroll
            for (int k = 0; k < 4; k++) acc[i][j][k] = 0.0f;

    uint32_t a_base = smem_u32(&As[0][0][0]);
    uint32_t b_base = smem_u32(&Bs[0][0][0]);
    const uint32_t STAGE_BYTES = 128 * ASTRIDE * 2;

    int lr_ = tid >> 2, seg = tid & 3;
    const __half* apz = a_ext + (size_t)(row0 + lr_) * K_EXT + seg * 8;
    const __half* bpz = b_ext + (size_t)(n0 + lr_) * K_EXT + seg * 8;
    uint32_t adst = a_base + lr_ * (ASTRIDE * 2) + seg * 16;
    uint32_t bdst = b_base + lr_ * (ASTRIDE * 2) + seg * 16;

#define LOADCH(c, buf)                                                       \
    {                                                                        \
        uint32_t so = (buf) * STAGE_BYTES;                                   \
        int ko = (c) * KCH;                                                  \
        _Pragma("unroll")                                                    \
        for (int i = 0; i < 4; i++) {                                        \
            CP16(adst + so + i * (32 * ASTRIDE * 2),                         \
                 (const char*)(apz + (size_t)i * 32 * K_EXT + ko));          \
            CP16(bdst + so + i * (32 * ASTRIDE * 2),                         \
                 (const char*)(bpz + (size_t)i * 32 * K_EXT + ko));          \
        }                                                                    \
        CPCOMMIT();                                                          \
    }

    LOADCH(0, 0);

    int lrow = lane & 15;
    int lcol8 = (lane >> 4) * 8;
    uint32_t a_lm = a_base + (warp_m * 64 + lrow) * (ASTRIDE * 2) + lcol8 * 2;
    uint32_t b_lm = b_base + (warp_n * 64 + lrow) * (ASTRIDE * 2) + lcol8 * 2;

#pragma unroll 1
    for (int c = 0; c < NCH; ++c) {
        int p = c & 1;
        if (c + 1 < NCH) {
            LOADCH(c + 1, 1 - p);
            CPWAIT(1);
        } else {
            CPWAIT(0);
        }
        __syncthreads();
        uint32_t so = p * STAGE_BYTES;
#pragma unroll
        for (int ks = 0; ks < 2; ks++) {
            unsigned af[4][4];
#pragma unroll
            for (int mt = 0; mt < 4; mt++)
                LDSM4(af[mt][0], af[mt][1], af[mt][2], af[mt][3],
                      a_lm + so + mt * 16 * (ASTRIDE * 2) + ks * 32);
            unsigned bf[4][4];
#pragma unroll
            for (int np = 0; np < 4; np++)
                LDSM4(bf[np][0], bf[np][1], bf[np][2], bf[np][3],
                      b_lm + so + np * 16 * (ASTRIDE * 2) + ks * 32);
#pragma unroll
            for (int mt = 0; mt < 4; mt++)
#pragma unroll
                for (int ntile = 0; ntile < 8; ntile++)
                    mma16816(acc[mt][ntile], af[mt],
                             bf[ntile >> 1][ntile & 1],
                             bf[ntile >> 1][(ntile & 1) + 2]);
        }
        __syncthreads();
    }

    // epilogue: d = (zsq + bsq) - 2*cross
    int rbase = row0 + warp_m * 64;
    int cbase = n0 + warp_n * 64;
    int rlo = rbase + (lane >> 2);
    int csub = (lane & 3) * 2;
#pragma unroll
    for (int mt = 0; mt < 4; mt++) {
        int r0 = rlo + mt * 16;
        int r1 = r0 + 8;
        float zs0 = g_zsq[r0], zs1 = g_zsq[r1];
        float* dp0 = g_d + (size_t)r0 * DSTRIDE;
        float* dp1 = g_d + (size_t)r1 * DSTRIDE;
#pragma unroll
        for (int ntile = 0; ntile < 8; ntile++) {
            int col = cbase + ntile * 8 + csub;
            float b0 = g_bsq[col], b1 = g_bsq[col + 1];
            float2 v0, v1;
            v0.x = (zs0 + b0) - 2.0f * acc[mt][ntile][0];
            v0.y = (zs0 + b1) - 2.0f * acc[mt][ntile][1];
            v1.x = (zs1 + b0) - 2.0f * acc[mt][ntile][2];
            v1.y = (zs1 + b1) - 2.0f * acc[mt][ntile][3];
            *(float2*)(dp0 + col) = v0;
            *(float2*)(dp1 + col) = v1;
        }
    }
#undef LOADCH
}

// ---------------------------------------------------------------------------
// k_scan5: branchless grouped cp.async scan (R10 design, 63 ns/step) with the
// hybrid fp32 recompute on interior near-ties (ia != ib2 only; boundary case
// is bit-exact in fp16, never recomputed).
// One block per batch; groups of 4 steps, 3 slots of 4x80B windows in flight.
// ---------------------------------------------------------------------------
__global__ void __launch_bounds__(32) k_scan5(const float* __restrict__ zf,
                                              const float* __restrict__ wf) {
    __shared__ __align__(16) char sbuf[1664];   // 3 slots * 320 B + scratch
    int b = blockIdx.x;
    int lane = threadIdx.x;
    int ibb = b * T_;

    int ia = g_ind[ibb];
    float coe = 0.0f;
    const float PC = 0.1f / 1024.0f;

    uint32_t sbase = smem_u32(sbuf);

    int act = lane < 20;
    int prow = act ? (lane / 5) : 0;
    int pchk = act ? (lane % 5) : 0;
    uint32_t dstoff = act ? (uint32_t)(prow * 80 + pchk * 16) : 960u;
    uint32_t psz = act ? 16u : 0u;
    const char* sp = (const char*)(g_d + (size_t)(ibb + 1 + prow) * DSTRIDE)
                   + pchk * 16;
    const size_t GSTRIDE = (size_t)4 * DSTRIDE * 4;   // 4 rows in bytes

    int ab0 = ia & ~3;
#pragma unroll
    for (int s = 0; s < 3; ++s) {
        CP16S(sbase + s * 320 + dstoff, sp + (size_t)ab0 * 4, psz);
        CPCOMMIT();
        sp += GSTRIDE;
    }

    uint32_t s0 = sbase, s1 = sbase + 320, s2 = sbase + 640;
    int b0 = ab0, b1 = ab0, b2 = ab0;
    int* gout = g_ind + ibb;
    int* sink = &g_sink[b];
    int t = 1;

#pragma unroll 1
    for (int g = 0; g < 256; ++g) {
        CPWAIT(2);                       // oldest group resident
        uint32_t adj = s0 - (uint32_t)(b0 * 4);
#pragma unroll
        for (int j = 0; j < 4; ++j) {
            float qh = lds_f(adj + j * 80 + ia * 4);
            int ib2 = min(ia + 1, NE_ - 1);
            float qn = lds_f(adj + j * 80 + ib2 * 4);
            float mar = qh - qn + coe;
            int tt = t + j;
            bool stay;
            if (fabsf(mar) < THETA && ia != ib2 && tt <= T_ - 1) {
                // exact fp32 recompute on the reference grid (rare)
                const float* zr = zf + (size_t)(ibb + tt) * E_ + lane * 8;
                const float* wA = wf + (size_t)ia * E_ + lane * 8;
                const float* wB = wf + (size_t)ib2 * E_ + lane * 8;
                float dotA = 0.0f, dotB = 0.0f;
#pragma unroll
                for (int e = 0; e < 8; e++) {
                    float zv_ = zr[e];
                    dotA += zv_ * wA[e];
                    dotB += zv_ * wB[e];
                }
#pragma unroll
                for (int o = 16; o > 0; o >>= 1) {
                    dotA += __shfl_xor_sync(0xffffffffu, dotA, o);
                    dotB += __shfl_xor_sync(0xffffffffu, dotB, o);
                }
                float zst = g_zsq[ibb + tt];
                float dAe = (zst + g_bsq[ia]) - 2.0f * dotA;
                float dBe = (zst + g_bsq[ib2]) - 2.0f * dotB;
                stay = (dAe <= dBe - coe);
            } else {
                stay = (mar <= 0.0f);
            }
            ia  = stay ? ia : ib2;
            coe = stay ? coe + PC : 0.0f;
            int* addr = (tt <= T_ - 1) ? (gout + tt) : sink;
            *addr = ia;
        }
        t += 4;
        int ab = ia & ~3;
        CP16S(s0 + dstoff, sp + (size_t)ab * 4, psz);
        CPCOMMIT();
        sp += GSTRIDE;
        uint32_t st = s0; s0 = s1; s1 = s2; s2 = st;
        b0 = b1; b1 = b2; b2 = ab;
    }
}

// ---------------------------------------------------------------------------
// k_post: gather z_q + indices + li, relu-sum loss over d rows (cols 0..1023)
// plus inline column 1024 (dot with book row 1024).
// ---------------------------------------------------------------------------
__global__ void __launch_bounds__(256) k_post(const float* __restrict__ z,
                                              const float* __restrict__ w,
                                              float* __restrict__ out,
                                              long long out_size) {
    __shared__ double wpart[8];
    int warp = threadIdx.x >> 5;
    int lane = threadIdx.x & 31;
    int row = blockIdx.x * 8 + warp;

    int idx = g_ind[row];
    const float* br = w + (size_t)idx * E_;
    const float* zrow = z + (size_t)row * E_;
    const float* wl = w + (size_t)NE_ * E_;      // book row 1024
    bool wz = (out_size >= (long long)ZQ_SIZE);

    float li = 0.0f, dq = 0.0f;
#pragma unroll
    for (int h = 0; h < 2; h++) {
        int off = h * 128 + 4 * lane;
        float4 q  = *(const float4*)(br + off);
        float4 zv = *(const float4*)(zrow + off);
        float4 wv = *(const float4*)(wl + off);
        float4 o;
        o.x = zv.x + (q.x - zv.x);
        o.y = zv.y + (q.y - zv.y);
        o.z = zv.z + (q.z - zv.z);
        o.w = zv.w + (q.w - zv.w);
        float dx = zv.x - q.x; li += dx * dx;
        dx = zv.y - q.y; li += dx * dx;
        dx = zv.z - q.z; li += dx * dx;
        dx = zv.w - q.w; li += dx * dx;
        dq += zv.x * wv.x + zv.y * wv.y + zv.z * wv.z + zv.w * wv.w;
        if (wz) *(float4*)(out + (size_t)row * E_ + off) = o;
    }
    li = warp_sum(li);
    dq = warp_sum(dq);
    li = __shfl_sync(0xffffffffu, li, 0);
    if (lane == 0 && out_size >= (long long)(IND_OFF + BT_))
        out[IND_OFF + row] = (float)idx;

    const float EPS_ = 1e-6f / 1024.0f;
    const float* drow = g_d + (size_t)row * DSTRIDE;
    float s = 0.0f;
#pragma unroll
    for (int m = 0; m < 8; m++) {
        float4 dv = *(const float4*)(drow + m * 128 + 4 * lane);
        s += fmaxf((li - dv.x) + EPS_, 0.0f);
        s += fmaxf((li - dv.y) + EPS_, 0.0f);
        s += fmaxf((li - dv.z) + EPS_, 0.0f);
        s += fmaxf((li - dv.w) + EPS_, 0.0f);
    }
    if (lane == 0) {
        float d1024 = (g_zsq[row] + g_bsq[NE_]) - 2.0f * dq;
        s += fmaxf((li - d1024) + EPS_, 0.0f);
    }
    s = warp_sum(s);
    if (lane == 0) wpart[warp] = (double)s;
    __syncthreads();
    if (threadIdx.x == 0) {
        double t = 0.0;
        for (int j = 0; j < 8; j++) t += wpart[j];
        g_part[blockIdx.x] = t;
    }
}

// ---------------------------------------------------------------------------
__global__ void k_final(float* __restrict__ out, long long out_size) {
    __shared__ double sd[256];
    __shared__ int smn[256], smx[256];
    int tid = threadIdx.x;
    double s = 0.0;
    for (int i = tid; i < NPOST; i += 256) s += g_part[i];
    int mn = 0x7fffffff, mx = -0x7fffffff;
    for (int i = tid; i < BT_; i += 256) {
        int v = g_ind[i];
        mn = min(mn, v);
        mx = max(mx, v);
    }
    sd[tid] = s; smn[tid] = mn; smx[tid] = mx;
    __syncthreads();
    for (int st = 128; st > 0; st >>= 1) {
        if (tid < st) {
            sd[tid] += sd[tid + st];
            smn[tid] = min(smn[tid], smn[tid + st]);
            smx[tid] = max(smx[tid], smx[tid + st]);
        }
        __syncthreads();
    }
    if (tid == 0) {
        float m = (float)(sd[0] / ((double)BT_ * (double)NB_));
        float loss = 0.25f * m + m;
        if (out_size > (long long)LOSS_OFF) out[LOSS_OFF] = loss;
        if (out_size > (long long)V_OFF)    out[V_OFF] = (float)(smx[0] - smn[0]);
    }
}

// ---------------------------------------------------------------------------
extern "C" void kernel_launch(void* const* d_in, const int* in_sizes, int n_in,
                              void* d_out, int out_size) {
    const float* z = (const float*)d_in[0];
    const float* w = (const float*)d_in[1];
    if (n_in >= 2 && in_sizes[0] == NB_ * E_ && in_sizes[1] == BT_ * E_) {
        const float* tmp = z; z = w; w = tmp;
    }
    float* out = (float*)d_out;
    long long osz = (long long)out_size;

    k_prep<<<(BT_ + NB_ + 7) / 8, 256>>>(z, w);
    k_first<<<B_, 256>>>(z, w);
    k_gemm<<<NGEMM, 128>>>();
    k_scan5<<<B_, 32>>>(z, w);
    k_post<<<NPOST, 256>>>(z, w, out, osz);
    k_final<<<1, 256>>>(out, osz);
}

// round 17
// speedup vs baseline: 3.8484x; 1.0297x over previous
#include <cuda_runtime.h>
#include <cuda_fp16.h>
#include <cstdint>

#define B_   16
#define T_   1024
#define E_   256
#define NB_  1025
#define BT_  16384
#define NE_  1024

#define ZQ_SIZE  (BT_ * E_)
#define LOSS_OFF ZQ_SIZE
#define IND_OFF  (ZQ_SIZE + 1)
#define V_OFF    (IND_OFF + BT_)

#define DSTRIDE  1024
#define NTILES_N 8               // 8 * 128 = 1024 cols (col 1024 handled in k_post)
#define NTILES_R 128
#define NGEMM    (NTILES_N * NTILES_R)   // 1024
#define NPOST    2048

#define K_EXT    256             // plain fp16 GEMM + hybrid-precision scan
#define KCH      32
#define NCH      (K_EXT / KCH)   // 8
#define ASTRIDE  40              // half elements per smem row (80 B)

#define THETA    2e-4f           // recompute trigger (interior near-ties only)

typedef unsigned long long ull;

__device__ int    g_ind[BT_];
__device__ int    g_sink[B_];
__device__ float  g_zsq[BT_];
__device__ float  g_bsq[1152];
__device__ float  g_d[(size_t)(BT_ + 16) * DSTRIDE];   // padded rows for scan tail
__device__ double g_part[NPOST];
__device__ __half a_ext[(size_t)BT_ * K_EXT];   // 8 MB
__device__ __half b_ext[(size_t)NB_ * K_EXT];   // 0.5 MB

static __device__ __forceinline__ float warp_sum(float v) {
#pragma unroll
    for (int o = 16; o > 0; o >>= 1) v += __shfl_xor_sync(0xffffffffu, v, o);
    return v;
}

static __device__ __forceinline__ uint32_t smem_u32(const void* p) {
    uint32_t a;
    asm("{ .reg .u64 t; cvta.to.shared.u64 t, %1; cvt.u32.u64 %0, t; }"
        : "=r"(a) : "l"(p));
    return a;
}

static __device__ __forceinline__ float lds_f(uint32_t addr) {
    float v;
    asm volatile("ld.shared.f32 %0, [%1];" : "=f"(v) : "r"(addr));
    return v;
}

#define CP16(dst, src) \
    asm volatile("cp.async.cg.shared.global [%0], [%1], 16;" :: "r"(dst), "l"(src))
#define CP16S(dst, src, sz) \
    asm volatile("cp.async.cg.shared.global [%0], [%1], 16, %2;" :: "r"(dst), "l"(src), "r"(sz))
#define CPCOMMIT() asm volatile("cp.async.commit_group;" ::: "memory")
#define CPWAIT(N)  asm volatile("cp.async.wait_group %0;" :: "n"(N) : "memory")

#define LDSM4(r0, r1, r2, r3, addr) \
    asm volatile("ldmatrix.sync.aligned.m8n8.x4.shared.b16 {%0,%1,%2,%3}, [%4];" \
                 : "=r"(r0), "=r"(r1), "=r"(r2), "=r"(r3) : "r"(addr))

static __device__ __forceinline__ void mma16816(float* c, const unsigned* a,
                                                unsigned b0, unsigned b1) {
    asm volatile(
        "mma.sync.aligned.m16n8k16.row.col.f32.f16.f16.f32 "
        "{%0,%1,%2,%3}, {%4,%5,%6,%7}, {%8,%9}, {%0,%1,%2,%3};"
        : "+f"(c[0]), "+f"(c[1]), "+f"(c[2]), "+f"(c[3])
        : "r"(a[0]), "r"(a[1]), "r"(a[2]), "r"(a[3]), "r"(b0), "r"(b1));
}

// ---------------------------------------------------------------------------
// k_prep: fused row norms + fp16 convert.
// ---------------------------------------------------------------------------
__global__ void k_prep(const float* __restrict__ z, const float* __restrict__ w) {
    int gw = (blockIdx.x * blockDim.x + threadIdx.x) >> 5;
    int lane = threadIdx.x & 31;
    if (gw >= BT_ + NB_) return;

    const float* src = (gw < BT_) ? (z + (size_t)gw * E_ + lane * 8)
                                  : (w + (size_t)(gw - BT_) * E_ + lane * 8);
    float4 a = *(const float4*)src;
    float4 b = *(const float4*)(src + 4);
    float f[8] = {a.x, a.y, a.z, a.w, b.x, b.y, b.z, b.w};

    float s = 0.0f;
    union { __half h[8]; uint4 v; } hi;
#pragma unroll
    for (int j = 0; j < 8; j++) {
        s += f[j] * f[j];
        hi.h[j] = __float2half_rn(f[j]);
    }
    s = warp_sum(s);

    if (gw < BT_) {
        *(uint4*)(a_ext + (size_t)gw * K_EXT + lane * 8) = hi.v;
        if (lane == 0) g_zsq[gw] = s;
    } else {
        *(uint4*)(b_ext + (size_t)(gw - BT_) * K_EXT + lane * 8) = hi.v;
        if (lane == 0) g_bsq[gw - BT_] = s;
    }
}

// ---------------------------------------------------------------------------
// argmin over d[b,0,:]  (exact fp32)
// ---------------------------------------------------------------------------
__global__ void k_first(const float* __restrict__ z, const float* __restrict__ w) {
    int b = blockIdx.x;
    __shared__ __align__(16) float zs[E_];
    __shared__ float sd[8];
    __shared__ int   sn[8];
    int tid = threadIdx.x;
    zs[tid] = z[(size_t)b * T_ * E_ + tid];
    __syncthreads();

    float zsq0 = g_zsq[b * T_];
    int warp = tid >> 5, lane = tid & 31;
    float4 za = *(const float4*)(zs + 4 * lane);
    float4 zb = *(const float4*)(zs + 128 + 4 * lane);

    float best = 3.4e38f;
    int bestn = 0x7fffffff;
    for (int n = warp; n < NB_; n += 8) {
        const float* wr = w + (size_t)n * E_;
        float4 wa = *(const float4*)(wr + 4 * lane);
        float4 wb = *(const float4*)(wr + 128 + 4 * lane);
        float p = za.x * wa.x + za.y * wa.y + za.z * wa.z + za.w * wa.w
                + zb.x * wb.x + zb.y * wb.y + zb.z * wb.z + zb.w * wb.w;
        p = warp_sum(p);
        float d = (zsq0 + g_bsq[n]) - 2.0f * p;
        if (d < best || (d == best && n < bestn)) { best = d; bestn = n; }
    }
    if (lane == 0) { sd[warp] = best; sn[warp] = bestn; }
    __syncthreads();
    if (tid == 0) {
        float bd = sd[0]; int bn = sn[0];
        for (int j = 1; j < 8; j++)
            if (sd[j] < bd || (sd[j] == bd && sn[j] < bn)) { bd = sd[j]; bn = sn[j]; }
        g_ind[b * T_] = min(bn, NE_ - 1);
    }
}

// ---------------------------------------------------------------------------
// fp16 GEMM via mma.sync: CTA 128x128, warp tile 64x64 (4 warps), K=256,
// double-buffered cp.async. d = (zsq + bsq) - 2*cross -> g_d.
// ---------------------------------------------------------------------------
__global__ void __launch_bounds__(128) k_gemm() {
    __shared__ __align__(16) __half As[2][128][ASTRIDE];
    __shared__ __align__(16) __half Bs[2][128][ASTRIDE];

    int tid = threadIdx.x;
    int wid = tid >> 5;
    int lane = tid & 31;
    int warp_m = wid >> 1;
    int warp_n = wid & 1;

    int bid = blockIdx.x;
    int nt0 = bid % NTILES_N;
    int rt  = bid / NTILES_N;
    int row0 = rt * 128;
    int n0   = nt0 * 128;

    float acc[4][8][4];
#pragma unroll
    for (int i = 0; i < 4; i++)
#pragma unroll
        for (int j = 0; j < 8; j++)
#pragma unroll
            for (int k = 0; k < 4; k++) acc[i][j][k] = 0.0f;

    uint32_t a_base = smem_u32(&As[0][0][0]);
    uint32_t b_base = smem_u32(&Bs[0][0][0]);
    const uint32_t STAGE_BYTES = 128 * ASTRIDE * 2;

    int lr_ = tid >> 2, seg = tid & 3;
    const __half* apz = a_ext + (size_t)(row0 + lr_) * K_EXT + seg * 8;
    const __half* bpz = b_ext + (size_t)(n0 + lr_) * K_EXT + seg * 8;
    uint32_t adst = a_base + lr_ * (ASTRIDE * 2) + seg * 16;
    uint32_t bdst = b_base + lr_ * (ASTRIDE * 2) + seg * 16;

#define LOADCH(c, buf)                                                       \
    {                                                                        \
        uint32_t so = (buf) * STAGE_BYTES;                                   \
        int ko = (c) * KCH;                                                  \
        _Pragma("unroll")                                                    \
        for (int i = 0; i < 4; i++) {                                        \
            CP16(adst + so + i * (32 * ASTRIDE * 2),                         \
                 (const char*)(apz + (size_t)i * 32 * K_EXT + ko));          \
            CP16(bdst + so + i * (32 * ASTRIDE * 2),                         \
                 (const char*)(bpz + (size_t)i * 32 * K_EXT + ko));          \
        }                                                                    \
        CPCOMMIT();                                                          \
    }

    LOADCH(0, 0);

    int lrow = lane & 15;
    int lcol8 = (lane >> 4) * 8;
    uint32_t a_lm = a_base + (warp_m * 64 + lrow) * (ASTRIDE * 2) + lcol8 * 2;
    uint32_t b_lm = b_base + (warp_n * 64 + lrow) * (ASTRIDE * 2) + lcol8 * 2;

#pragma unroll 1
    for (int c = 0; c < NCH; ++c) {
        int p = c & 1;
        if (c + 1 < NCH) {
            LOADCH(c + 1, 1 - p);
            CPWAIT(1);
        } else {
            CPWAIT(0);
        }
        __syncthreads();
        uint32_t so = p * STAGE_BYTES;
#pragma unroll
        for (int ks = 0; ks < 2; ks++) {
            unsigned af[4][4];
#pragma unroll
            for (int mt = 0; mt < 4; mt++)
                LDSM4(af[mt][0], af[mt][1], af[mt][2], af[mt][3],
                      a_lm + so + mt * 16 * (ASTRIDE * 2) + ks * 32);
            unsigned bf[4][4];
#pragma unroll
            for (int np = 0; np < 4; np++)
                LDSM4(bf[np][0], bf[np][1], bf[np][2], bf[np][3],
                      b_lm + so + np * 16 * (ASTRIDE * 2) + ks * 32);
#pragma unroll
            for (int mt = 0; mt < 4; mt++)
#pragma unroll
                for (int ntile = 0; ntile < 8; ntile++)
                    mma16816(acc[mt][ntile], af[mt],
                             bf[ntile >> 1][ntile & 1],
                             bf[ntile >> 1][(ntile & 1) + 2]);
        }
        __syncthreads();
    }

    // epilogue: d = (zsq + bsq) - 2*cross
    int rbase = row0 + warp_m * 64;
    int cbase = n0 + warp_n * 64;
    int rlo = rbase + (lane >> 2);
    int csub = (lane & 3) * 2;
#pragma unroll
    for (int mt = 0; mt < 4; mt++) {
        int r0 = rlo + mt * 16;
        int r1 = r0 + 8;
        float zs0 = g_zsq[r0], zs1 = g_zsq[r1];
        float* dp0 = g_d + (size_t)r0 * DSTRIDE;
        float* dp1 = g_d + (size_t)r1 * DSTRIDE;
#pragma unroll
        for (int ntile = 0; ntile < 8; ntile++) {
            int col = cbase + ntile * 8 + csub;
            float b0 = g_bsq[col], b1 = g_bsq[col + 1];
            float2 v0, v1;
            v0.x = (zs0 + b0) - 2.0f * acc[mt][ntile][0];
            v0.y = (zs0 + b1) - 2.0f * acc[mt][ntile][1];
            v1.x = (zs1 + b0) - 2.0f * acc[mt][ntile][2];
            v1.y = (zs1 + b1) - 2.0f * acc[mt][ntile][3];
            *(float2*)(dp0 + col) = v0;
            *(float2*)(dp1 + col) = v1;
        }
    }
#undef LOADCH
}

// ---------------------------------------------------------------------------
// k_scan6: speculative lane-parallel scan. One block per batch.
// Each group of 4 steps: lane l simulates decision pattern (l & 15) entirely
// from the resident smem window (no intra-group load->decision chain),
// checks self-consistency against actual margins; ballot finds the unique
// consistent lane; SHFL broadcasts the final state. Hybrid fp32 recompute on
// interior near-ties via rare whole-group serial redo (decisions == R16).
// ---------------------------------------------------------------------------
__global__ void __launch_bounds__(32) k_scan6(const float* __restrict__ zf,
                                              const float* __restrict__ wf) {
    __shared__ __align__(16) char sbuf[1664];   // 3 slots * 320 B + scratch
    int b = blockIdx.x;
    int lane = threadIdx.x;
    int ibb = b * T_;

    int ia = g_ind[ibb];
    float coe = 0.0f;
    const float PC = 0.1f / 1024.0f;

    uint32_t sbase = smem_u32(sbuf);

    int act = lane < 20;
    int prow = act ? (lane / 5) : 0;
    int pchk = act ? (lane % 5) : 0;
    uint32_t dstoff = act ? (uint32_t)(prow * 80 + pchk * 16) : 960u;
    uint32_t psz = act ? 16u : 0u;
    const char* sp = (const char*)(g_d + (size_t)(ibb + 1 + prow) * DSTRIDE)
                   + pchk * 16;
    const size_t GSTRIDE = (size_t)4 * DSTRIDE * 4;   // 4 rows in bytes

    int ab0 = ia & ~3;
#pragma unroll
    for (int s = 0; s < 3; ++s) {
        CP16S(sbase + s * 320 + dstoff, sp + (size_t)ab0 * 4, psz);
        CPCOMMIT();
        sp += GSTRIDE;
    }

    uint32_t s0 = sbase, s1 = sbase + 320, s2 = sbase + 640;
    int b0 = ab0, b1 = ab0, b2 = ab0;
    int* gout = g_ind + ibb;
    int* sink = &g_sink[b];
    int t = 1;
    int pat = lane & 15;

#pragma unroll 1
    for (int g = 0; g < 256; ++g) {
        CPWAIT(2);                       // oldest group resident
        uint32_t adj = s0 - (uint32_t)(b0 * 4);

        // ---- speculative pattern simulation (all addresses known upfront) ----
        int ia_j = ia;
        float coe_j = coe;
        bool ok = true, near = false;
        int st[4];
#pragma unroll
        for (int j = 0; j < 4; ++j) {
            int ibj = min(ia_j + 1, NE_ - 1);
            float qh = lds_f(adj + j * 80 + ia_j * 4);
            float qn = lds_f(adj + j * 80 + ibj * 4);
            float mar = qh - qn + coe_j;
            bool dec = (mar <= 0.0f);           // actual decision (stay)
            bool pj = ((pat >> j) & 1) != 0;    // pattern decision (stay)
            bool guard = (t + j <= T_ - 1);
            ok = ok && ((dec == pj) || !guard);
            near = near || ((fabsf(mar) < THETA) && (ia_j != ibj) && guard);
            ia_j  = pj ? ia_j : ibj;
            coe_j = pj ? coe_j + PC : 0.0f;
            st[j] = ia_j;
        }
        unsigned mok   = __ballot_sync(0xffffffffu, ok);
        unsigned mnear = __ballot_sync(0xffffffffu, ok && near);
        int L = __ffs(mok) - 1;
        int ia_new = __shfl_sync(0xffffffffu, ia_j, L);
        float coe_new = __shfl_sync(0xffffffffu, coe_j, L);

        if (mnear == 0) {
            if (lane == L) {
#pragma unroll
                for (int j = 0; j < 4; ++j) {
                    int tt = t + j;
                    int* addr = (tt <= T_ - 1) ? (gout + tt) : sink;
                    *addr = st[j];
                }
            }
            ia = ia_new;
            coe = coe_new;
        } else {
            // ---- rare: serial redo with exact fp32 recompute ----
#pragma unroll 1
            for (int j = 0; j < 4; ++j) {
                int ib2 = min(ia + 1, NE_ - 1);
                float qh = lds_f(adj + j * 80 + ia * 4);
                float qn = lds_f(adj + j * 80 + ib2 * 4);
                float mar = qh - qn + coe;
                int tt = t + j;
                bool stay;
                if (fabsf(mar) < THETA && ia != ib2 && tt <= T_ - 1) {
                    const float* zr = zf + (size_t)(ibb + tt) * E_ + lane * 8;
                    const float* wA = wf + (size_t)ia * E_ + lane * 8;
                    const float* wB = wf + (size_t)ib2 * E_ + lane * 8;
                    float dotA = 0.0f, dotB = 0.0f;
#pragma unroll
                    for (int e = 0; e < 8; e++) {
                        float zv_ = zr[e];
                        dotA += zv_ * wA[e];
                        dotB += zv_ * wB[e];
                    }
#pragma unroll
                    for (int o = 16; o > 0; o >>= 1) {
                        dotA += __shfl_xor_sync(0xffffffffu, dotA, o);
                        dotB += __shfl_xor_sync(0xffffffffu, dotB, o);
                    }
                    float zst = g_zsq[ibb + tt];
                    float dAe = (zst + g_bsq[ia]) - 2.0f * dotA;
                    float dBe = (zst + g_bsq[ib2]) - 2.0f * dotB;
                    stay = (dAe <= dBe - coe);
                } else {
                    stay = (mar <= 0.0f);
                }
                ia  = stay ? ia : ib2;
                coe = stay ? coe + PC : 0.0f;
                int* addr = (tt <= T_ - 1) ? (gout + tt) : sink;
                *addr = ia;
            }
        }

        t += 4;
        int ab = ia & ~3;
        CP16S(s0 + dstoff, sp + (size_t)ab * 4, psz);
        CPCOMMIT();
        sp += GSTRIDE;
        uint32_t stm = s0; s0 = s1; s1 = s2; s2 = stm;
        b0 = b1; b1 = b2; b2 = ab;
    }
}

// ---------------------------------------------------------------------------
// k_post: gather z_q + indices + li, relu-sum loss over d rows (cols 0..1023)
// plus inline column 1024 (dot with book row 1024).
// ---------------------------------------------------------------------------
__global__ void __launch_bounds__(256) k_post(const float* __restrict__ z,
                                              const float* __restrict__ w,
                                              float* __restrict__ out,
                                              long long out_size) {
    __shared__ double wpart[8];
    int warp = threadIdx.x >> 5;
    int lane = threadIdx.x & 31;
    int row = blockIdx.x * 8 + warp;

    int idx = g_ind[row];
    const float* br = w + (size_t)idx * E_;
    const float* zrow = z + (size_t)row * E_;
    const float* wl = w + (size_t)NE_ * E_;      // book row 1024
    bool wz = (out_size >= (long long)ZQ_SIZE);

    float li = 0.0f, dq = 0.0f;
#pragma unroll
    for (int h = 0; h < 2; h++) {
        int off = h * 128 + 4 * lane;
        float4 q  = *(const float4*)(br + off);
        float4 zv = *(const float4*)(zrow + off);
        float4 wv = *(const float4*)(wl + off);
        float4 o;
        o.x = zv.x + (q.x - zv.x);
        o.y = zv.y + (q.y - zv.y);
        o.z = zv.z + (q.z - zv.z);
        o.w = zv.w + (q.w - zv.w);
        float dx = zv.x - q.x; li += dx * dx;
        dx = zv.y - q.y; li += dx * dx;
        dx = zv.z - q.z; li += dx * dx;
        dx = zv.w - q.w; li += dx * dx;
        dq += zv.x * wv.x + zv.y * wv.y + zv.z * wv.z + zv.w * wv.w;
        if (wz) *(float4*)(out + (size_t)row * E_ + off) = o;
    }
    li = warp_sum(li);
    dq = warp_sum(dq);
    li = __shfl_sync(0xffffffffu, li, 0);
    if (lane == 0 && out_size >= (long long)(IND_OFF + BT_))
        out[IND_OFF + row] = (float)idx;

    const float EPS_ = 1e-6f / 1024.0f;
    const float* drow = g_d + (size_t)row * DSTRIDE;
    float s = 0.0f;
#pragma unroll
    for (int m = 0; m < 8; m++) {
        float4 dv = *(const float4*)(drow + m * 128 + 4 * lane);
        s += fmaxf((li - dv.x) + EPS_, 0.0f);
        s += fmaxf((li - dv.y) + EPS_, 0.0f);
        s += fmaxf((li - dv.z) + EPS_, 0.0f);
        s += fmaxf((li - dv.w) + EPS_, 0.0f);
    }
    if (lane == 0) {
        float d1024 = (g_zsq[row] + g_bsq[NE_]) - 2.0f * dq;
        s += fmaxf((li - d1024) + EPS_, 0.0f);
    }
    s = warp_sum(s);
    if (lane == 0) wpart[warp] = (double)s;
    __syncthreads();
    if (threadIdx.x == 0) {
        double t = 0.0;
        for (int j = 0; j < 8; j++) t += wpart[j];
        g_part[blockIdx.x] = t;
    }
}

// ---------------------------------------------------------------------------
__global__ void k_final(float* __restrict__ out, long long out_size) {
    __shared__ double sd[256];
    __shared__ int smn[256], smx[256];
    int tid = threadIdx.x;
    double s = 0.0;
    for (int i = tid; i < NPOST; i += 256) s += g_part[i];
    int mn = 0x7fffffff, mx = -0x7fffffff;
    for (int i = tid; i < BT_; i += 256) {
        int v = g_ind[i];
        mn = min(mn, v);
        mx = max(mx, v);
    }
    sd[tid] = s; smn[tid] = mn; smx[tid] = mx;
    __syncthreads();
    for (int st = 128; st > 0; st >>= 1) {
        if (tid < st) {
            sd[tid] += sd[tid + st];
            smn[tid] = min(smn[tid], smn[tid + st]);
            smx[tid] = max(smx[tid], smx[tid + st]);
        }
        __syncthreads();
    }
    if (tid == 0) {
        float m = (float)(sd[0] / ((double)BT_ * (double)NB_));
        float loss = 0.25f * m + m;
        if (out_size > (long long)LOSS_OFF) out[LOSS_OFF] = loss;
        if (out_size > (long long)V_OFF)    out[V_OFF] = (float)(smx[0] - smn[0]);
    }
}

// ---------------------------------------------------------------------------
extern "C" void kernel_launch(void* const* d_in, const int* in_sizes, int n_in,
                              void* d_out, int out_size) {
    const float* z = (const float*)d_in[0];
    const float* w = (const float*)d_in[1];
    if (n_in >= 2 && in_sizes[0] == NB_ * E_ && in_sizes[1] == BT_ * E_) {
        const float* tmp = z; z = w; w = tmp;
    }
    float* out = (float*)d_out;
    long long osz = (long long)out_size;

    k_prep<<<(BT_ + NB_ + 7) / 8, 256>>>(z, w);
    k_first<<<B_, 256>>>(z, w);
    k_gemm<<<NGEMM, 128>>>();
    k_scan6<<<B_, 32>>>(z, w);
    k_post<<<NPOST, 256>>>(z, w, out, osz);
    k_final<<<1, 256>>>(out, osz);
}